// round 2
// baseline (speedup 1.0000x reference)
#include <cuda_runtime.h>
#include <math.h>

#define SEQ   512
#define BATCH 64
#define INP   64
#define HID   1024
#define G4    (4 * HID)

#define NBLK  128          // HID / JT blocks, one per SM (<=148 -> co-resident)
#define NTHR  256
#define JT    8            // h-columns per block
#define BK    32           // K slab for h staging

#define WS_STRIDE 36       // padded row stride for ws   [1024][36] (16B aligned)
#define HS_STRIDE 66       // padded row stride for hs   [32][66]   (8B aligned)
#define GS_STRIDE 65       // padded row stride for gsm  [32][65]

// ---------------------------------------------------------------------------
// Static device scratch
// ---------------------------------------------------------------------------
__device__ float g_xg[(size_t)SEQ * BATCH * G4];     // input-gate precompute
__device__ float g_h1[(size_t)SEQ * BATCH * HID];    // layer-0 hidden sequence
__device__ float g_hzero[BATCH * HID];               // zeros for h_{-1}
__device__ unsigned g_bar_count;
__device__ unsigned g_bar_gen;

// ---------------------------------------------------------------------------
__global__ void init_state_kernel() {
    int i = blockIdx.x * blockDim.x + threadIdx.x;
    if (i < BATCH * HID) g_hzero[i] = 0.f;
    if (i == 0) g_bar_count = 0u;
}

// Software grid barrier (all blocks co-resident by construction).
__device__ __forceinline__ void grid_barrier(unsigned nb) {
    __threadfence();
    __syncthreads();
    if (threadIdx.x == 0) {
        unsigned gen = atomicAdd(&g_bar_gen, 0u);
        __threadfence();
        unsigned t = atomicAdd(&g_bar_count, 1u);
        if (t == nb - 1u) {
            atomicExch(&g_bar_count, 0u);
            __threadfence();
            atomicAdd(&g_bar_gen, 1u);
        } else {
            while (atomicAdd(&g_bar_gen, 0u) == gen) { }
        }
    }
    __syncthreads();
}

// ---------------------------------------------------------------------------
// C[M][4096] = A[M][K] @ W[4096][K]^T + (b1 + b2)   (fp32 SIMT, 64x64 tiles)
// ---------------------------------------------------------------------------
__global__ void sgemm_bias_kernel(const float* __restrict__ A,
                                  const float* __restrict__ W,
                                  const float* __restrict__ b1,
                                  const float* __restrict__ b2,
                                  float* __restrict__ C,
                                  int M, int K) {
    const int BKg = 16;
    __shared__ float As[BKg][64];
    __shared__ float Bs[BKg][64];

    int tid = threadIdx.x;
    int tx = tid & 15;
    int ty = tid >> 4;
    int m0 = blockIdx.y * 64;
    int n0 = blockIdx.x * 64;

    float acc[4][4];
#pragma unroll
    for (int i = 0; i < 4; i++)
#pragma unroll
        for (int j = 0; j < 4; j++) acc[i][j] = 0.f;

    int lr = tid >> 2;
    int lc = tid & 3;

    for (int k0 = 0; k0 < K; k0 += BKg) {
        float4 va = *(const float4*)(A + (size_t)(m0 + lr) * K + k0 + lc * 4);
        As[lc * 4 + 0][lr] = va.x;
        As[lc * 4 + 1][lr] = va.y;
        As[lc * 4 + 2][lr] = va.z;
        As[lc * 4 + 3][lr] = va.w;
        float4 vb = *(const float4*)(W + (size_t)(n0 + lr) * K + k0 + lc * 4);
        Bs[lc * 4 + 0][lr] = vb.x;
        Bs[lc * 4 + 1][lr] = vb.y;
        Bs[lc * 4 + 2][lr] = vb.z;
        Bs[lc * 4 + 3][lr] = vb.w;
        __syncthreads();

#pragma unroll
        for (int kk = 0; kk < BKg; kk++) {
            float a[4], b[4];
#pragma unroll
            for (int i = 0; i < 4; i++) a[i] = As[kk][ty * 4 + i];
#pragma unroll
            for (int j = 0; j < 4; j++) b[j] = Bs[kk][tx * 4 + j];
#pragma unroll
            for (int i = 0; i < 4; i++)
#pragma unroll
                for (int j = 0; j < 4; j++) acc[i][j] += a[i] * b[j];
        }
        __syncthreads();
    }

#pragma unroll
    for (int i = 0; i < 4; i++) {
        int m = m0 + ty * 4 + i;
#pragma unroll
        for (int j = 0; j < 4; j++) {
            int n = n0 + tx * 4 + j;
            C[(size_t)m * G4 + n] = acc[i][j] + b1[n] + b2[n];
        }
    }
}

// ---------------------------------------------------------------------------
// Persistent LSTM layer: all 512 timesteps in one kernel.
// Block bx owns h-columns [bx*8, bx*8+8) for all 4 gates and all 64 batches.
// Whh slice kept in SMEM for the whole sequence; c kept in registers.
// ---------------------------------------------------------------------------
__global__ void __launch_bounds__(NTHR, 1)
lstm_layer_kernel(const float* __restrict__ xg,      // [SEQ, B, 4H]
                  const float* __restrict__ Whh,     // [4H, H]
                  const float* __restrict__ hzero,   // [B, H] zeros
                  float* __restrict__ hseq)          // [SEQ, B, H] out
{
    extern __shared__ float smem[];
    float* ws  = smem;                            // [1024][WS_STRIDE]
    float* hs  = ws + 1024 * WS_STRIDE;           // [BK][HS_STRIDE]
    float* gsm = hs + BK * HS_STRIDE;             // [32][GS_STRIDE]

    const int tid = threadIdx.x;
    const int j0  = blockIdx.x * JT;
    const unsigned nb = gridDim.x;

    // ---- One-time: load this block's Whh slice, transposed to ws[k][r] ----
    // r = g*8 + jl  ->  global row g*HID + j0 + jl
    {
        int r  = tid >> 3;          // 0..31
        int kc = tid & 7;           // 8 chunks of 128 k each
        int g  = r >> 3, jl = r & 7;
        const float4* src =
            (const float4*)(Whh + (size_t)(g * HID + j0 + jl) * HID + kc * 128);
#pragma unroll
        for (int i = 0; i < 32; i++) {
            float4 v = src[i];
            int k = kc * 128 + i * 4;
            ws[(k + 0) * WS_STRIDE + r] = v.x;
            ws[(k + 1) * WS_STRIDE + r] = v.y;
            ws[(k + 2) * WS_STRIDE + r] = v.z;
            ws[(k + 3) * WS_STRIDE + r] = v.w;
        }
    }
    __syncthreads();

    const int bq = tid & 31;        // batch pair: b = bq*2 + i
    const int rq = tid >> 5;        // row quad:   r = rq*4 + j
    const int hb = tid >> 2;        // 0..63 h row for staging
    const int hc = tid & 3;         // float4 slot (and slot+4)

    float creg[2] = {0.f, 0.f};     // cell state for pairs p = tid, tid+256

    for (int t = 0; t < SEQ; t++) {
        const float* h_in = (t == 0) ? hzero
                                     : (hseq + (size_t)(t - 1) * BATCH * HID);
        const float* xg_t = xg + (size_t)t * BATCH * G4;

        float acc[2][4];
#pragma unroll
        for (int i = 0; i < 2; i++)
#pragma unroll
            for (int j = 0; j < 4; j++) acc[i][j] = 0.f;

        for (int k0 = 0; k0 < HID; k0 += BK) {
            // stage h slab -> hs[k][b]
            const float4* hrow = (const float4*)(h_in + (size_t)hb * HID + k0);
#pragma unroll
            for (int i = 0; i < 2; i++) {
                int c4 = hc + i * 4;
                float4 v = hrow[c4];
                int k = c4 * 4;
                hs[(k + 0) * HS_STRIDE + hb] = v.x;
                hs[(k + 1) * HS_STRIDE + hb] = v.y;
                hs[(k + 2) * HS_STRIDE + hb] = v.z;
                hs[(k + 3) * HS_STRIDE + hb] = v.w;
            }
            __syncthreads();

#pragma unroll
            for (int kk = 0; kk < BK; kk++) {
                float2 a = *(const float2*)&hs[kk * HS_STRIDE + bq * 2];
                float4 w = *(const float4*)&ws[(k0 + kk) * WS_STRIDE + rq * 4];
                acc[0][0] += a.x * w.x;
                acc[0][1] += a.x * w.y;
                acc[0][2] += a.x * w.z;
                acc[0][3] += a.x * w.w;
                acc[1][0] += a.y * w.x;
                acc[1][1] += a.y * w.y;
                acc[1][2] += a.y * w.z;
                acc[1][3] += a.y * w.w;
            }
            __syncthreads();
        }

        // stage gate partials -> gsm[r][b]
#pragma unroll
        for (int i = 0; i < 2; i++)
#pragma unroll
            for (int j = 0; j < 4; j++)
                gsm[(rq * 4 + j) * GS_STRIDE + bq * 2 + i] = acc[i][j];
        __syncthreads();

        // pointwise cell update: pairs p = tid + 256*q
        float* h_out = hseq + (size_t)t * BATCH * HID;
#pragma unroll
        for (int q = 0; q < 2; q++) {
            int p  = tid + NTHR * q;
            int b  = p >> 3;
            int jl = p & 7;
            int j  = j0 + jl;
            const float* xr = xg_t + (size_t)b * G4 + j;
            float ig = gsm[(0 * JT + jl) * GS_STRIDE + b] + xr[0 * HID];
            float fg = gsm[(1 * JT + jl) * GS_STRIDE + b] + xr[1 * HID];
            float gg = gsm[(2 * JT + jl) * GS_STRIDE + b] + xr[2 * HID];
            float og = gsm[(3 * JT + jl) * GS_STRIDE + b] + xr[3 * HID];
            ig = 1.f / (1.f + expf(-ig));
            fg = 1.f / (1.f + expf(-fg));
            gg = tanhf(gg);
            og = 1.f / (1.f + expf(-og));
            float cn = fg * creg[q] + ig * gg;
            creg[q] = cn;
            h_out[(size_t)b * HID + j] = og * tanhf(cn);
        }

        grid_barrier(nb);   // h_out visible everywhere before next step
    }
}

// ---------------------------------------------------------------------------
__global__ void final_linear_kernel(const float* __restrict__ h_last,
                                    const float* __restrict__ Wl,
                                    const float* __restrict__ bl,
                                    float* __restrict__ y) {
    int b = blockIdx.x;
    __shared__ float red[128];
    float s = 0.f;
    for (int k = threadIdx.x; k < HID; k += 128)
        s += h_last[(size_t)b * HID + k] * Wl[k];
    red[threadIdx.x] = s;
    __syncthreads();
    for (int off = 64; off > 0; off >>= 1) {
        if (threadIdx.x < off) red[threadIdx.x] += red[threadIdx.x + off];
        __syncthreads();
    }
    if (threadIdx.x == 0) y[b] = red[0] + bl[0];
}

// ---------------------------------------------------------------------------
extern "C" void kernel_launch(void* const* d_in, const int* in_sizes, int n_in,
                              void* d_out, int out_size) {
    (void)in_sizes; (void)n_in; (void)out_size;
    const float* x    = (const float*)d_in[0];
    const float* Wih0 = (const float*)d_in[1];
    const float* Whh0 = (const float*)d_in[2];
    const float* bih0 = (const float*)d_in[3];
    const float* bhh0 = (const float*)d_in[4];
    const float* Wih1 = (const float*)d_in[5];
    const float* Whh1 = (const float*)d_in[6];
    const float* bih1 = (const float*)d_in[7];
    const float* bhh1 = (const float*)d_in[8];
    const float* Wlin = (const float*)d_in[9];
    const float* blin = (const float*)d_in[10];

    float* out      = (float*)d_out;
    float* lstm_out = out;                                  // [SEQ, BATCH, HID]
    float* ypred    = out + (size_t)SEQ * BATCH * HID;      // [BATCH]

    float *xg, *h1, *hzero;
    cudaGetSymbolAddress((void**)&xg,    g_xg);
    cudaGetSymbolAddress((void**)&h1,    g_h1);
    cudaGetSymbolAddress((void**)&hzero, g_hzero);

    const int smem_bytes =
        (1024 * WS_STRIDE + BK * HS_STRIDE + 32 * GS_STRIDE) * (int)sizeof(float);
    cudaFuncSetAttribute(lstm_layer_kernel,
                         cudaFuncAttributeMaxDynamicSharedMemorySize, smem_bytes);

    const int M = SEQ * BATCH;
    dim3 gemm_grid(G4 / 64, M / 64);

    // ---- Layer 0 ----
    sgemm_bias_kernel<<<gemm_grid, 256>>>(x, Wih0, bih0, bhh0, xg, M, INP);
    init_state_kernel<<<(BATCH * HID + 255) / 256, 256>>>();
    lstm_layer_kernel<<<NBLK, NTHR, smem_bytes>>>(xg, Whh0, hzero, h1);

    // ---- Layer 1 ----
    sgemm_bias_kernel<<<gemm_grid, 256>>>(h1, Wih1, bih1, bhh1, xg, M, HID);
    init_state_kernel<<<(BATCH * HID + 255) / 256, 256>>>();
    lstm_layer_kernel<<<NBLK, NTHR, smem_bytes>>>(xg, Whh1, hzero, lstm_out);

    // ---- Head ----
    final_linear_kernel<<<BATCH, 128>>>(lstm_out + (size_t)(SEQ - 1) * BATCH * HID,
                                        Wlin, blin, ypred);
}